// round 14
// baseline (speedup 1.0000x reference)
#include <cuda_runtime.h>
#include <cuda_fp16.h>
#include <cstdint>
#include <math.h>

// Problem constants (fixed by setup_inputs)
#define B_   4
#define N_   1024
#define C_   1024
#define H_   16
#define D_   64
#define NC_  256
#define M_   1280            // NC_ + N_
#define KVT  20              // M_/64 kv tiles

// ---------------------------------------------------------------------------
// Scratch (allocation-free rule: __device__ globals)
// ---------------------------------------------------------------------------
__device__ __half g_qkvh[(size_t)B_ * N_ * 3 * C_];           // GEMM1 out (Q pre-scaled, log2-domain)
__device__ __half g_xh[(size_t)B_ * N_ * C_];                 // x fp16
__device__ __half g_wqkv[(size_t)3 * C_ * C_];                // Q-rows scaled by 0.125*log2e
__device__ __half g_wproj[(size_t)C_ * C_];
__device__ __half g_ah[(size_t)B_ * N_ * C_];                 // attn out fp16
__device__ __half g_kh[(size_t)B_ * H_ * M_ * D_];
__device__ __half g_vth[(size_t)B_ * H_ * D_ * M_];           // V^T [d][kv]

// ---------------------------------------------------------------------------
// Helpers (sm_100 baseline PTX only)
// ---------------------------------------------------------------------------
__device__ __forceinline__ uint32_t smem_u32(const void* p) {
    uint32_t a;
    asm("{ .reg .u64 t; cvta.to.shared.u64 t, %1; cvt.u32.u64 %0, t; }" : "=r"(a) : "l"(p));
    return a;
}
__device__ __forceinline__ void cpa16(uint32_t d, const void* g) {
    asm volatile("cp.async.cg.shared.global [%0], [%1], 16;" :: "r"(d), "l"(g));
}
__device__ __forceinline__ void cpa_commit() { asm volatile("cp.async.commit_group;"); }
template <int n> __device__ __forceinline__ void cpa_wait() {
    asm volatile("cp.async.wait_group %0;" :: "n"(n));
}
__device__ __forceinline__ uint32_t sw128(uint32_t off) { return off ^ ((off >> 3) & 0x70); }

__device__ __forceinline__ void ldsm_x4(uint32_t* r, uint32_t addr) {
    asm volatile("ldmatrix.sync.aligned.m8n8.x4.shared.b16 {%0,%1,%2,%3}, [%4];"
        : "=r"(r[0]), "=r"(r[1]), "=r"(r[2]), "=r"(r[3]) : "r"(addr));
}
__device__ __forceinline__ void mma_fp16(float* d, const uint32_t* a,
                                         uint32_t b0, uint32_t b1) {
    asm volatile(
        "mma.sync.aligned.m16n8k16.row.col.f32.f16.f16.f32 "
        "{%0,%1,%2,%3},{%4,%5,%6,%7},{%8,%9},{%0,%1,%2,%3};"
        : "+f"(d[0]), "+f"(d[1]), "+f"(d[2]), "+f"(d[3])
        : "r"(a[0]), "r"(a[1]), "r"(a[2]), "r"(a[3]), "r"(b0), "r"(b1));
}
__device__ __forceinline__ uint32_t pack_h2(float a, float b) {
    __half2 t = __floats2half2_rn(a, b);
    return *(uint32_t*)&t;
}
__device__ __forceinline__ float fexp2(float x) {
    float y;
    asm("ex2.approx.ftz.f32 %0, %1;" : "=f"(y) : "f"(x));
    return y;
}

// ---------------------------------------------------------------------------
// One-shot fp32 -> fp16 conversion of x, w_qkv (Q rows scaled), w_proj
// ---------------------------------------------------------------------------
#define N4X (B_ * N_ * C_ / 4)       // 1048576
#define N4Q (3 * C_ * C_ / 4)        // 786432
#define N4P (C_ * C_ / 4)            // 262144
#define N4ALL (N4X + N4Q + N4P)
#define QSCALE (0.125f * 1.4426950408889634f)   // softmax scale * log2e

__global__ void decomp_all(const float* __restrict__ x,
                           const float* __restrict__ wq,
                           const float* __restrict__ wp,
                           __half* __restrict__ xh,
                           __half* __restrict__ wqh,
                           __half* __restrict__ wph) {
    int i = blockIdx.x * blockDim.x + threadIdx.x;
    if (i < N4X) {
        float4 v = ((const float4*)x)[i];
        ((uint32_t*)xh)[i * 2 + 0] = pack_h2(v.x, v.y);
        ((uint32_t*)xh)[i * 2 + 1] = pack_h2(v.z, v.w);
    } else if (i < N4X + N4Q) {
        int j = i - N4X;
        float4 v = ((const float4*)wq)[j];
        float s = (j < C_ * C_ / 4) ? QSCALE : 1.0f;
        ((uint32_t*)wqh)[j * 2 + 0] = pack_h2(v.x * s, v.y * s);
        ((uint32_t*)wqh)[j * 2 + 1] = pack_h2(v.z * s, v.w * s);
    } else if (i < N4ALL) {
        int j = i - N4X - N4Q;
        float4 v = ((const float4*)wp)[j];
        ((uint32_t*)wph)[j * 2 + 0] = pack_h2(v.x, v.y);
        ((uint32_t*)wph)[j * 2 + 1] = pack_h2(v.z, v.w);
    }
}

// ---------------------------------------------------------------------------
// Prep: K fp16 [bh][M][D] + Vt fp16 [bh][D][M]; sources: ctx fp32 / qkv fp16
// ---------------------------------------------------------------------------
__global__ void prepkv_kernel(const __half* __restrict__ qkv, const float* __restrict__ ctx,
                              __half* __restrict__ kh, __half* __restrict__ vth) {
    __shared__ float sv[64][65];
    const int tid = threadIdx.x;
    const int kv0 = blockIdx.x * 64;
    const int bh  = blockIdx.y;
    const int b = bh >> 4, h = bh & 15;

#pragma unroll
    for (int it = 0; it < 4; it++) {
        int idx = tid + it * 256;
        int r  = idx >> 4;
        int dc = idx & 15;
        int kv = kv0 + r;
        float kx[4], vx[4];
        if (kv < NC_) {
            const float* base = ctx + (((size_t)(b * NC_ + kv)) * 2 + 0) * C_ + h * D_ + dc * 4;
            float4 kvec = *(const float4*)base;
            float4 vvec = *(const float4*)(base + C_);
            kx[0] = kvec.x; kx[1] = kvec.y; kx[2] = kvec.z; kx[3] = kvec.w;
            vx[0] = vvec.x; vx[1] = vvec.y; vx[2] = vvec.z; vx[3] = vvec.w;
        } else {
            const __half* base = qkv + (((size_t)(b * N_ + kv - NC_)) * 3 + 1) * C_ + h * D_ + dc * 4;
            __half2 k0 = *(const __half2*)base, k1 = *(const __half2*)(base + 2);
            __half2 w0 = *(const __half2*)(base + C_), w1 = *(const __half2*)(base + C_ + 2);
            kx[0] = __low2float(k0); kx[1] = __high2float(k0);
            kx[2] = __low2float(k1); kx[3] = __high2float(k1);
            vx[0] = __low2float(w0); vx[1] = __high2float(w0);
            vx[2] = __low2float(w1); vx[3] = __high2float(w1);
        }
        size_t o = (((size_t)bh) * M_ + kv) * D_ + dc * 4;
        *(uint32_t*)(kh + o)     = pack_h2(kx[0], kx[1]);
        *(uint32_t*)(kh + o + 2) = pack_h2(kx[2], kx[3]);
        sv[r][dc * 4 + 0] = vx[0]; sv[r][dc * 4 + 1] = vx[1];
        sv[r][dc * 4 + 2] = vx[2]; sv[r][dc * 4 + 3] = vx[3];
    }
    __syncthreads();

    {
        int d  = tid >> 2;
        int q4 = (tid & 3) * 16;
        size_t o = ((size_t)bh) * D_ * M_ + (size_t)d * M_ + kv0 + q4;
#pragma unroll
        for (int k2 = 0; k2 < 8; k2++) {
            *(uint32_t*)(vth + o + k2 * 2) =
                pack_h2(sv[q4 + k2 * 2][d], sv[q4 + k2 * 2 + 1][d]);
        }
    }
}

// ---------------------------------------------------------------------------
// mma.sync fp16 GEMM: 128x128 CTA, 4 warps (2x2) each 64x64, 128 threads,
// K-chunk 64, 3-stage cp.async, 2 CTAs/SM, separable swizzle.
// ---------------------------------------------------------------------------
#define GKC 64
#define TILE_B 16384
#define STAGE_BYTES (2 * TILE_B)           // A, B
#define GEMM_SMEM (3 * STAGE_BYTES + 1024)

template <bool OUTHALF>
__global__ __launch_bounds__(128, 2) void gemm_mma(
    const __half* __restrict__ A, const __half* __restrict__ Bm,
    const float* __restrict__ bias,
    float* __restrict__ Cf, __half* __restrict__ Ch,
    int M, int N, int K)
{
    extern __shared__ char sm[];
    const uint32_t tiles = (smem_u32(sm) + 1023) & ~1023u;

    const int tid  = threadIdx.x;
    const int lane = tid & 31;
    const int wid  = tid >> 5;           // 0..3
    const int wm0  = (wid >> 1) * 64;
    const int wn0  = (wid & 1) * 64;
    const int bm = blockIdx.y * 128;
    const int bn = blockIdx.x * 128;

    // hoisted per-thread load addressing (8 slots per operand)
    uint32_t gsw[8];
    uint32_t goA[8], goB[8];     // element offsets (32-bit safe: < 16M)
#pragma unroll
    for (int i = 0; i < 8; i++) {
        int idx = tid + i * 128;
        int r = idx >> 3;
        int c = idx & 7;
        gsw[i] = sw128((uint32_t)(r * 128 + c * 16));
        goA[i] = (uint32_t)((bm + r) * K + c * 8);
        goB[i] = (uint32_t)((bn + r) * K + c * 8);
    }
    auto gload = [&](int k0, uint32_t st) {
#pragma unroll
        for (int i = 0; i < 8; i++) {
            cpa16(st + gsw[i],          A  + goA[i] + k0);
            cpa16(st + TILE_B + gsw[i], Bm + goB[i] + k0);
        }
    };

    const int lr = lane & 15;
    const int lc = (lane >> 4) << 4;
    const uint32_t xv = (uint32_t)((lr & 7) << 4);

    uint32_t arow[4], brow[4], colx[4];
#pragma unroll
    for (int mt = 0; mt < 4; mt++) arow[mt] = (uint32_t)((wm0 + mt * 16 + lr) * 128);
#pragma unroll
    for (int ng = 0; ng < 4; ng++) brow[ng] = (uint32_t)((wn0 + ng * 16 + lr) * 128) + TILE_B;
#pragma unroll
    for (int kk = 0; kk < 4; kk++) colx[kk] = ((uint32_t)(kk * 32 + lc)) ^ xv;

    float acc[4][8][4];
#pragma unroll
    for (int i = 0; i < 4; i++)
#pragma unroll
        for (int j = 0; j < 8; j++)
#pragma unroll
            for (int t = 0; t < 4; t++) acc[i][j][t] = 0.0f;

    const int NCH = K / GKC;

    gload(0, tiles);
    cpa_commit();
    gload(GKC, tiles + STAGE_BYTES);
    cpa_commit();

    int stage = 0;
    for (int k = 0; k < NCH; k++) {
        if (k + 1 < NCH) cpa_wait<1>(); else cpa_wait<0>();
        __syncthreads();
        if (k + 2 < NCH) {
            int ns = (stage + 2); if (ns >= 3) ns -= 3;
            gload((k + 2) * GKC, tiles + ns * STAGE_BYTES);
            cpa_commit();
        }

        const uint32_t sb = tiles + stage * STAGE_BYTES;

#pragma unroll
        for (int kk = 0; kk < 4; kk++) {
            uint32_t af[4][4], bf[4][4];
#pragma unroll
            for (int mt = 0; mt < 4; mt++)
                ldsm_x4(af[mt], sb + arow[mt] + colx[kk]);
#pragma unroll
            for (int ng = 0; ng < 4; ng++)
                ldsm_x4(bf[ng], sb + brow[ng] + colx[kk]);
#pragma unroll
            for (int mt = 0; mt < 4; mt++)
#pragma unroll
                for (int nt = 0; nt < 8; nt++) {
                    const int ng = nt >> 1, s = nt & 1;
                    mma_fp16(acc[mt][nt], af[mt], bf[ng][s], bf[ng][2 + s]);
                }
        }
        if (++stage >= 3) stage = 0;
    }

    const int gq = lane >> 2;
    const int tg = lane & 3;
#pragma unroll
    for (int mt = 0; mt < 4; mt++) {
        const int row0 = bm + wm0 + mt * 16 + gq;
#pragma unroll
        for (int nt = 0; nt < 8; nt++) {
            const int col = bn + wn0 + nt * 8 + tg * 2;
            if (OUTHALF) {
                *(uint32_t*)(Ch + (size_t)row0 * N + col) =
                    pack_h2(acc[mt][nt][0], acc[mt][nt][1]);
                *(uint32_t*)(Ch + (size_t)(row0 + 8) * N + col) =
                    pack_h2(acc[mt][nt][2], acc[mt][nt][3]);
            } else {
                float b0v = bias[col], b1v = bias[col + 1];
                float2 v0 = make_float2(acc[mt][nt][0] + b0v, acc[mt][nt][1] + b1v);
                float2 v1 = make_float2(acc[mt][nt][2] + b0v, acc[mt][nt][3] + b1v);
                *(float2*)(Cf + (size_t)row0 * N + col)       = v0;
                *(float2*)(Cf + (size_t)(row0 + 8) * N + col) = v1;
            }
        }
    }
}

// ---------------------------------------------------------------------------
// Flash attention: 4 warps x 32 query rows (CTA = 128 q), 128 threads,
// 3-stage cp.async, base-2 softmax (fp32 ex2), rescale-skip warp vote.
// smem: Q 16KB + 3 stages x 16KB = 64KB; 2 CTAs/SM
// ---------------------------------------------------------------------------
#define AT_STAGE 16384
#define AT_SMEM (16384 + 3 * AT_STAGE + 1024)

__global__ __launch_bounds__(128, 2) void attn_mma(
    const __half* __restrict__ qkv, const __half* __restrict__ Kh,
    const __half* __restrict__ Vth, __half* __restrict__ oh)
{
    extern __shared__ char sm[];
    const uint32_t base = (smem_u32(sm) + 1023) & ~1023u;
    const uint32_t sQ = base;
    const uint32_t sStage = base + 16384;

    const int tid  = threadIdx.x;
    const int lane = tid & 31;
    const int wid  = tid >> 5;           // 0..3
    const int qt = blockIdx.x;
    const int h  = blockIdx.y;
    const int b  = blockIdx.z;
    const int bh = b * H_ + h;

    const __half* qg  = qkv + ((size_t)(b * N_ + qt * 128) * 3) * C_ + h * D_;
    const __half* khg = Kh + (size_t)bh * M_ * D_;
    const __half* vhg = Vth + (size_t)bh * D_ * M_;

    // hoisted per-thread prefetch addressing
    uint32_t lso[4], lko[4], lvo[4];
#pragma unroll
    for (int i = 0; i < 4; i++) {
        int idx = tid + i * 128;
        int r = idx >> 3;
        int c = idx & 7;
        lso[i] = sw128((uint32_t)(r * 128 + c * 16));
        lko[i] = (uint32_t)(r * D_ + c * 8);
        lvo[i] = (uint32_t)(r * M_ + c * 8);
    }
    auto prefetch = [&](int kv0, uint32_t st) {
        const __half* kb = khg + (size_t)kv0 * D_;
        const __half* vb = vhg + kv0;
#pragma unroll
        for (int i = 0; i < 4; i++) {
            cpa16(st + lso[i],        kb + lko[i]);
            cpa16(st + 8192 + lso[i], vb + lvo[i]);
        }
    };

    // Q tile: 128 rows x 128B (row stride 3C in gmem)
#pragma unroll
    for (int i = 0; i < 8; i++) {
        int idx = tid + i * 128;
        int r = idx >> 3;        // 0..127
        int c = idx & 7;
        cpa16(sQ + sw128((uint32_t)(r * 128 + c * 16)),
              qg + (size_t)r * 3 * C_ + c * 8);
    }
    prefetch(0, sStage);
    cpa_commit();
    prefetch(64, sStage + AT_STAGE);
    cpa_commit();

    const int lr = lane & 15;
    const int lc = (lane >> 4) << 4;
    const int w32 = wid * 32;
    const uint32_t xv = (uint32_t)((lr & 7) << 4);

    uint32_t rowo[4], colx[4];
#pragma unroll
    for (int ng = 0; ng < 4; ng++) rowo[ng] = (uint32_t)((ng * 16 + lr) * 128);
#pragma unroll
    for (int kk = 0; kk < 4; kk++) colx[kk] = ((uint32_t)(kk * 32 + lc)) ^ xv;

    uint32_t qf[2][4][4];
    float O[2][8][4];
#pragma unroll
    for (int mf = 0; mf < 2; mf++)
#pragma unroll
        for (int nt = 0; nt < 8; nt++)
#pragma unroll
            for (int t = 0; t < 4; t++) O[mf][nt][t] = 0.0f;
    float mrow[2][2], lrow[2][2];
#pragma unroll
    for (int mf = 0; mf < 2; mf++) {
        mrow[mf][0] = -1e30f; mrow[mf][1] = -1e30f;
        lrow[mf][0] = 0.0f;   lrow[mf][1] = 0.0f;
    }

    int stage = 0;
    for (int kt = 0; kt < KVT; kt++) {
        if (kt + 1 < KVT) cpa_wait<1>(); else cpa_wait<0>();
        __syncthreads();
        if (kt + 2 < KVT) {
            int ns = stage + 2; if (ns >= 3) ns -= 3;
            prefetch((kt + 2) * 64, sStage + ns * AT_STAGE);
            cpa_commit();
        }

        if (kt == 0) {
#pragma unroll
            for (int mf = 0; mf < 2; mf++) {
                const uint32_t qrow = sQ + (uint32_t)((w32 + mf * 16 + lr) * 128);
#pragma unroll
                for (int kk = 0; kk < 4; kk++)
                    ldsm_x4(qf[mf][kk], qrow + colx[kk]);
            }
        }

        const uint32_t tK = sStage + stage * AT_STAGE;
        const uint32_t tV = tK + 8192;

        // ---- S = Q . K^T (log2 domain) ----
        float S[2][8][4];
#pragma unroll
        for (int mf = 0; mf < 2; mf++)
#pragma unroll
            for (int nt = 0; nt < 8; nt++)
#pragma unroll
                for (int t = 0; t < 4; t++) S[mf][nt][t] = 0.0f;

#pragma unroll
        for (int kk = 0; kk < 4; kk++) {
            uint32_t bf[4][4];
#pragma unroll
            for (int ng = 0; ng < 4; ng++)
                ldsm_x4(bf[ng], tK + rowo[ng] + colx[kk]);
#pragma unroll
            for (int mf = 0; mf < 2; mf++)
#pragma unroll
                for (int ng = 0; ng < 4; ng++)
#pragma unroll
                    for (int s = 0; s < 2; s++)
                        mma_fp16(S[mf][ng * 2 + s], qf[mf][kk], bf[ng][s], bf[ng][2 + s]);
        }

        // ---- online softmax (base 2, fp32 ex2), rescale-skip vote ----
        uint32_t ph[2][4][4];
#pragma unroll
        for (int mf = 0; mf < 2; mf++) {
            float mt0 = -1e30f, mt1 = -1e30f;
#pragma unroll
            for (int nt = 0; nt < 8; nt++) {
                mt0 = fmaxf(mt0, fmaxf(S[mf][nt][0], S[mf][nt][1]));
                mt1 = fmaxf(mt1, fmaxf(S[mf][nt][2], S[mf][nt][3]));
            }
            mt0 = fmaxf(mt0, __shfl_xor_sync(0xffffffffu, mt0, 1));
            mt0 = fmaxf(mt0, __shfl_xor_sync(0xffffffffu, mt0, 2));
            mt1 = fmaxf(mt1, __shfl_xor_sync(0xffffffffu, mt1, 1));
            mt1 = fmaxf(mt1, __shfl_xor_sync(0xffffffffu, mt1, 2));

            float mn0 = fmaxf(mrow[mf][0], mt0), mn1 = fmaxf(mrow[mf][1], mt1);
            float a0 = fexp2(mrow[mf][0] - mn0), a1 = fexp2(mrow[mf][1] - mn1);
            mrow[mf][0] = mn0; mrow[mf][1] = mn1;

            float rs0 = 0.0f, rs1 = 0.0f;
#pragma unroll
            for (int nt = 0; nt < 8; nt++) {
                S[mf][nt][0] = fexp2(S[mf][nt][0] - mn0);
                S[mf][nt][1] = fexp2(S[mf][nt][1] - mn0);
                S[mf][nt][2] = fexp2(S[mf][nt][2] - mn1);
                S[mf][nt][3] = fexp2(S[mf][nt][3] - mn1);
                rs0 += S[mf][nt][0] + S[mf][nt][1];
                rs1 += S[mf][nt][2] + S[mf][nt][3];
            }
            rs0 += __shfl_xor_sync(0xffffffffu, rs0, 1);
            rs0 += __shfl_xor_sync(0xffffffffu, rs0, 2);
            rs1 += __shfl_xor_sync(0xffffffffu, rs1, 1);
            rs1 += __shfl_xor_sync(0xffffffffu, rs1, 2);
            lrow[mf][0] = lrow[mf][0] * a0 + rs0;
            lrow[mf][1] = lrow[mf][1] * a1 + rs1;

            // rescale only when the max actually moved anywhere in the warp
            bool skip = __all_sync(0xffffffffu, (a0 == 1.0f) && (a1 == 1.0f));
            if (!skip) {
#pragma unroll
                for (int nt = 0; nt < 8; nt++) {
                    O[mf][nt][0] *= a0; O[mf][nt][1] *= a0;
                    O[mf][nt][2] *= a1; O[mf][nt][3] *= a1;
                }
            }

#pragma unroll
            for (int j = 0; j < 4; j++) {
                ph[mf][j][0] = pack_h2(S[mf][2 * j][0],     S[mf][2 * j][1]);
                ph[mf][j][1] = pack_h2(S[mf][2 * j][2],     S[mf][2 * j][3]);
                ph[mf][j][2] = pack_h2(S[mf][2 * j + 1][0], S[mf][2 * j + 1][1]);
                ph[mf][j][3] = pack_h2(S[mf][2 * j + 1][2], S[mf][2 * j + 1][3]);
            }
        }

        // ---- O += P . Vt^T ----
#pragma unroll
        for (int j = 0; j < 4; j++) {
            uint32_t vf[4][4];
#pragma unroll
            for (int ng = 0; ng < 4; ng++)
                ldsm_x4(vf[ng], tV + rowo[ng] + colx[j]);
#pragma unroll
            for (int mf = 0; mf < 2; mf++)
#pragma unroll
                for (int ng = 0; ng < 4; ng++)
#pragma unroll
                    for (int s = 0; s < 2; s++)
                        mma_fp16(O[mf][ng * 2 + s], ph[mf][j], vf[ng][s], vf[ng][2 + s]);
        }
        if (++stage >= 3) stage = 0;
    }

    // ---- epilogue ----
    const int g  = lane >> 2;
    const int tg = lane & 3;
#pragma unroll
    for (int mf = 0; mf < 2; mf++) {
        const float inv0 = 1.0f / lrow[mf][0], inv1 = 1.0f / lrow[mf][1];
        const int n0 = qt * 128 + w32 + mf * 16 + g;
#pragma unroll
        for (int nt = 0; nt < 8; nt++) {
            const int col = h * D_ + nt * 8 + tg * 2;
            *(uint32_t*)(oh + (size_t)(b * N_ + n0) * C_ + col) =
                pack_h2(O[mf][nt][0] * inv0, O[mf][nt][1] * inv0);
            *(uint32_t*)(oh + (size_t)(b * N_ + n0 + 8) * C_ + col) =
                pack_h2(O[mf][nt][2] * inv1, O[mf][nt][3] * inv1);
        }
    }
}

// ---------------------------------------------------------------------------
extern "C" void kernel_launch(void* const* d_in, const int* in_sizes, int n_in,
                              void* d_out, int out_size) {
    const float* x      = (const float*)d_in[0];
    const float* ctx    = (const float*)d_in[1];
    const float* w_qkv  = (const float*)d_in[2];
    const float* w_proj = (const float*)d_in[3];
    const float* b_proj = (const float*)d_in[4];
    float* out = (float*)d_out;

    void *p;
    cudaGetSymbolAddress(&p, g_qkvh);  __half* qkvh = (__half*)p;
    cudaGetSymbolAddress(&p, g_xh);    __half* xh   = (__half*)p;
    cudaGetSymbolAddress(&p, g_wqkv);  __half* wq   = (__half*)p;
    cudaGetSymbolAddress(&p, g_wproj); __half* wp   = (__half*)p;
    cudaGetSymbolAddress(&p, g_ah);    __half* ah   = (__half*)p;
    cudaGetSymbolAddress(&p, g_kh);    __half* kh   = (__half*)p;
    cudaGetSymbolAddress(&p, g_vth);   __half* vth  = (__half*)p;

    cudaFuncSetAttribute(gemm_mma<true>,  cudaFuncAttributeMaxDynamicSharedMemorySize, GEMM_SMEM);
    cudaFuncSetAttribute(gemm_mma<false>, cudaFuncAttributeMaxDynamicSharedMemorySize, GEMM_SMEM);
    cudaFuncSetAttribute(attn_mma,        cudaFuncAttributeMaxDynamicSharedMemorySize, AT_SMEM);

    // 0) convert inputs/weights to fp16 (Q-rows of w_qkv carry 0.125*log2e)
    decomp_all<<<(N4ALL + 255) / 256, 256>>>(x, w_qkv, w_proj, xh, wq, wp);

    // 1) QKV projection -> fp16 qkv
    {
        dim3 grid(3 * C_ / 128, B_ * N_ / 128);
        gemm_mma<true><<<grid, 128, GEMM_SMEM>>>(xh, wq, nullptr, nullptr, qkvh,
                                                 B_ * N_, 3 * C_, C_);
    }

    // 1.5) K gather + V transpose
    {
        dim3 grid(KVT, B_ * H_);
        prepkv_kernel<<<grid, 256>>>(qkvh, ctx, kh, vth);
    }

    // 2) Attention (base-2 softmax, rescale-skip)
    {
        dim3 grid(N_ / 128, H_, B_);
        attn_mma<<<grid, 128, AT_SMEM>>>(qkvh, kh, vth, ah);
    }

    // 3) Output projection with bias -> fp32 out
    {
        dim3 grid(C_ / 128, B_ * N_ / 128);
        gemm_mma<false><<<grid, 128, GEMM_SMEM>>>(ah, wp, b_proj, out, nullptr,
                                                  B_ * N_, C_, C_);
    }
}

// round 15
// speedup vs baseline: 1.1424x; 1.1424x over previous
#include <cuda_runtime.h>
#include <cuda_fp16.h>
#include <cstdint>
#include <math.h>

// Problem constants (fixed by setup_inputs)
#define B_   4
#define N_   1024
#define C_   1024
#define H_   16
#define D_   64
#define NC_  256
#define M_   1280            // NC_ + N_
#define KVT  20              // M_/64 kv tiles

// ---------------------------------------------------------------------------
// Scratch (allocation-free rule: __device__ globals)
// ---------------------------------------------------------------------------
__device__ __half g_qkvh[(size_t)B_ * N_ * 3 * C_];           // GEMM1 out (Q pre-scaled, log2-domain)
__device__ __half g_ctxh[(size_t)B_ * NC_ * 2 * C_];          // context fp16
__device__ __half g_xh[(size_t)B_ * N_ * C_];                 // x fp16
__device__ __half g_wqkv[(size_t)3 * C_ * C_];                // Q-rows scaled by 0.125*log2e
__device__ __half g_wproj[(size_t)C_ * C_];
__device__ __half g_ah[(size_t)B_ * N_ * C_];                 // attn out fp16

// ---------------------------------------------------------------------------
// Helpers (sm_100 baseline PTX only)
// ---------------------------------------------------------------------------
__device__ __forceinline__ uint32_t smem_u32(const void* p) {
    uint32_t a;
    asm("{ .reg .u64 t; cvta.to.shared.u64 t, %1; cvt.u32.u64 %0, t; }" : "=r"(a) : "l"(p));
    return a;
}
__device__ __forceinline__ void cpa16(uint32_t d, const void* g) {
    asm volatile("cp.async.cg.shared.global [%0], [%1], 16;" :: "r"(d), "l"(g));
}
__device__ __forceinline__ void cpa_commit() { asm volatile("cp.async.commit_group;"); }
template <int n> __device__ __forceinline__ void cpa_wait() {
    asm volatile("cp.async.wait_group %0;" :: "n"(n));
}
__device__ __forceinline__ uint32_t sw128(uint32_t off) { return off ^ ((off >> 3) & 0x70); }

__device__ __forceinline__ void ldsm_x4(uint32_t* r, uint32_t addr) {
    asm volatile("ldmatrix.sync.aligned.m8n8.x4.shared.b16 {%0,%1,%2,%3}, [%4];"
        : "=r"(r[0]), "=r"(r[1]), "=r"(r[2]), "=r"(r[3]) : "r"(addr));
}
__device__ __forceinline__ void ldsm_x4_t(uint32_t* r, uint32_t addr) {
    asm volatile("ldmatrix.sync.aligned.m8n8.x4.trans.shared.b16 {%0,%1,%2,%3}, [%4];"
        : "=r"(r[0]), "=r"(r[1]), "=r"(r[2]), "=r"(r[3]) : "r"(addr));
}
__device__ __forceinline__ void mma_fp16(float* d, const uint32_t* a,
                                         uint32_t b0, uint32_t b1) {
    asm volatile(
        "mma.sync.aligned.m16n8k16.row.col.f32.f16.f16.f32 "
        "{%0,%1,%2,%3},{%4,%5,%6,%7},{%8,%9},{%0,%1,%2,%3};"
        : "+f"(d[0]), "+f"(d[1]), "+f"(d[2]), "+f"(d[3])
        : "r"(a[0]), "r"(a[1]), "r"(a[2]), "r"(a[3]), "r"(b0), "r"(b1));
}
__device__ __forceinline__ uint32_t pack_h2(float a, float b) {
    __half2 t = __floats2half2_rn(a, b);
    return *(uint32_t*)&t;
}
__device__ __forceinline__ float fexp2(float x) {
    float y;
    asm("ex2.approx.ftz.f32 %0, %1;" : "=f"(y) : "f"(x));
    return y;
}

// ---------------------------------------------------------------------------
// One-shot fp32 -> fp16 conversion of ctx, x, w_qkv (Q rows scaled), w_proj
// ---------------------------------------------------------------------------
#define N4C (B_ * NC_ * 2 * C_ / 4)  // 524288
#define N4X (B_ * N_ * C_ / 4)       // 1048576
#define N4Q (3 * C_ * C_ / 4)        // 786432
#define N4P (C_ * C_ / 4)            // 262144
#define N4ALL (N4C + N4X + N4Q + N4P)
#define QSCALE (0.125f * 1.4426950408889634f)   // softmax scale * log2e

__global__ void decomp_all(const float* __restrict__ ctx,
                           const float* __restrict__ x,
                           const float* __restrict__ wq,
                           const float* __restrict__ wp,
                           __half* __restrict__ ctxh,
                           __half* __restrict__ xh,
                           __half* __restrict__ wqh,
                           __half* __restrict__ wph) {
    int i = blockIdx.x * blockDim.x + threadIdx.x;
    if (i < N4C) {
        float4 v = ((const float4*)ctx)[i];
        ((uint32_t*)ctxh)[i * 2 + 0] = pack_h2(v.x, v.y);
        ((uint32_t*)ctxh)[i * 2 + 1] = pack_h2(v.z, v.w);
    } else if (i < N4C + N4X) {
        int j = i - N4C;
        float4 v = ((const float4*)x)[j];
        ((uint32_t*)xh)[j * 2 + 0] = pack_h2(v.x, v.y);
        ((uint32_t*)xh)[j * 2 + 1] = pack_h2(v.z, v.w);
    } else if (i < N4C + N4X + N4Q) {
        int j = i - N4C - N4X;
        float4 v = ((const float4*)wq)[j];
        float s = (j < C_ * C_ / 4) ? QSCALE : 1.0f;
        ((uint32_t*)wqh)[j * 2 + 0] = pack_h2(v.x * s, v.y * s);
        ((uint32_t*)wqh)[j * 2 + 1] = pack_h2(v.z * s, v.w * s);
    } else if (i < N4ALL) {
        int j = i - N4C - N4X - N4Q;
        float4 v = ((const float4*)wp)[j];
        ((uint32_t*)wph)[j * 2 + 0] = pack_h2(v.x, v.y);
        ((uint32_t*)wph)[j * 2 + 1] = pack_h2(v.z, v.w);
    }
}

// ---------------------------------------------------------------------------
// mma.sync fp16 GEMM: 128x128 CTA, 4 warps (2x2) each 64x64, 128 threads,
// K-chunk 64, 3-stage cp.async, 2 CTAs/SM, separable swizzle. (R10 form)
// ---------------------------------------------------------------------------
#define GKC 64
#define TILE_B 16384
#define STAGE_BYTES (2 * TILE_B)           // A, B
#define GEMM_SMEM (3 * STAGE_BYTES + 1024)

__device__ __forceinline__ void load_tile128(const __half* __restrict__ src,
                                             int rbase, int K, int k0,
                                             uint32_t tb, int tid) {
#pragma unroll
    for (int i = 0; i < 8; i++) {
        int idx = tid + i * 128;
        int r = idx >> 3;
        int c = idx & 7;
        const void* g = src + (size_t)(rbase + r) * K + k0 + c * 8;
        cpa16(tb + sw128((uint32_t)(r * 128 + c * 16)), g);
    }
}

template <bool OUTHALF>
__global__ __launch_bounds__(128, 2) void gemm_mma(
    const __half* __restrict__ A, const __half* __restrict__ Bm,
    const float* __restrict__ bias,
    float* __restrict__ Cf, __half* __restrict__ Ch,
    int M, int N, int K)
{
    extern __shared__ char sm[];
    const uint32_t tiles = (smem_u32(sm) + 1023) & ~1023u;

    const int tid  = threadIdx.x;
    const int lane = tid & 31;
    const int wid  = tid >> 5;           // 0..3
    const int wm0  = (wid >> 1) * 64;
    const int wn0  = (wid & 1) * 64;
    const int bm = blockIdx.y * 128;
    const int bn = blockIdx.x * 128;

    const int lr = lane & 15;
    const int lc = (lane >> 4) << 4;
    const uint32_t xv = (uint32_t)((lr & 7) << 4);

    uint32_t arow[4], brow[4], colx[4];
#pragma unroll
    for (int mt = 0; mt < 4; mt++) arow[mt] = (uint32_t)((wm0 + mt * 16 + lr) * 128);
#pragma unroll
    for (int ng = 0; ng < 4; ng++) brow[ng] = (uint32_t)((wn0 + ng * 16 + lr) * 128) + TILE_B;
#pragma unroll
    for (int kk = 0; kk < 4; kk++) colx[kk] = ((uint32_t)(kk * 32 + lc)) ^ xv;

    float acc[4][8][4];
#pragma unroll
    for (int i = 0; i < 4; i++)
#pragma unroll
        for (int j = 0; j < 8; j++)
#pragma unroll
            for (int t = 0; t < 4; t++) acc[i][j][t] = 0.0f;

    const int NCH = K / GKC;

    {
        load_tile128(A,  bm, K, 0, tiles,          tid);
        load_tile128(Bm, bn, K, 0, tiles + TILE_B, tid);
        cpa_commit();
        load_tile128(A,  bm, K, GKC, tiles + STAGE_BYTES,          tid);
        load_tile128(Bm, bn, K, GKC, tiles + STAGE_BYTES + TILE_B, tid);
        cpa_commit();
    }

    int stage = 0;
    for (int k = 0; k < NCH; k++) {
        if (k + 1 < NCH) cpa_wait<1>(); else cpa_wait<0>();
        __syncthreads();
        if (k + 2 < NCH) {
            int ns = (stage + 2); if (ns >= 3) ns -= 3;
            uint32_t st = tiles + ns * STAGE_BYTES;
            const int k0 = (k + 2) * GKC;
            load_tile128(A,  bm, K, k0, st,          tid);
            load_tile128(Bm, bn, K, k0, st + TILE_B, tid);
            cpa_commit();
        }

        const uint32_t sb = tiles + stage * STAGE_BYTES;

#pragma unroll
        for (int kk = 0; kk < 4; kk++) {
            uint32_t af[4][4], bf[4][4];
#pragma unroll
            for (int mt = 0; mt < 4; mt++)
                ldsm_x4(af[mt], sb + arow[mt] + colx[kk]);
#pragma unroll
            for (int ng = 0; ng < 4; ng++)
                ldsm_x4(bf[ng], sb + brow[ng] + colx[kk]);
#pragma unroll
            for (int mt = 0; mt < 4; mt++)
#pragma unroll
                for (int nt = 0; nt < 8; nt++) {
                    const int ng = nt >> 1, s = nt & 1;
                    mma_fp16(acc[mt][nt], af[mt], bf[ng][s], bf[ng][2 + s]);
                }
        }
        if (++stage >= 3) stage = 0;
    }

    const int gq = lane >> 2;
    const int tg = lane & 3;
#pragma unroll
    for (int mt = 0; mt < 4; mt++) {
        const int row0 = bm + wm0 + mt * 16 + gq;
#pragma unroll
        for (int nt = 0; nt < 8; nt++) {
            const int col = bn + wn0 + nt * 8 + tg * 2;
            if (OUTHALF) {
                *(uint32_t*)(Ch + (size_t)row0 * N + col) =
                    pack_h2(acc[mt][nt][0], acc[mt][nt][1]);
                *(uint32_t*)(Ch + (size_t)(row0 + 8) * N + col) =
                    pack_h2(acc[mt][nt][2], acc[mt][nt][3]);
            } else {
                float b0v = bias[col], b1v = bias[col + 1];
                float2 v0 = make_float2(acc[mt][nt][0] + b0v, acc[mt][nt][1] + b1v);
                float2 v1 = make_float2(acc[mt][nt][2] + b0v, acc[mt][nt][3] + b1v);
                *(float2*)(Cf + (size_t)row0 * N + col)       = v0;
                *(float2*)(Cf + (size_t)(row0 + 8) * N + col) = v1;
            }
        }
    }
}

// ---------------------------------------------------------------------------
// Flash attention: 4 warps x 32 query rows (CTA = 128 q), 128 threads,
// 3-stage cp.async DIRECTLY from ctxh/qkvh (no prep pass), base-2 softmax.
// K tile [kv][d] (non-trans ldsm), V tile [kv][d] (trans ldsm for B-frag).
// smem: Q 16KB + 3 stages x 16KB = 64KB; 2 CTAs/SM
// ---------------------------------------------------------------------------
#define AT_STAGE 16384
#define AT_SMEM (16384 + 3 * AT_STAGE + 1024)

__global__ __launch_bounds__(128, 2) void attn_mma(
    const __half* __restrict__ qkv, const __half* __restrict__ ctxh,
    __half* __restrict__ oh)
{
    extern __shared__ char sm[];
    const uint32_t base = (smem_u32(sm) + 1023) & ~1023u;
    const uint32_t sQ = base;
    const uint32_t sStage = base + 16384;

    const int tid  = threadIdx.x;
    const int lane = tid & 31;
    const int wid  = tid >> 5;           // 0..3
    const int qt = blockIdx.x;
    const int h  = blockIdx.y;
    const int b  = blockIdx.z;

    const __half* qg = qkv + ((size_t)(b * N_ + qt * 128) * 3) * C_ + h * D_;

    // per-tile K/V source select (uniform: tiles 0..3 ctx, 4..19 projected)
    auto prefetch = [&](int kv0, uint32_t st) {
        const __half* kb;
        int stride;
        if (kv0 < NC_) {
            kb = ctxh + ((size_t)(b * NC_ + kv0) * 2) * C_ + h * D_;
            stride = 2 * C_;
        } else {
            kb = qkv + ((size_t)(b * N_ + kv0 - NC_) * 3) * C_ + C_ + h * D_;
            stride = 3 * C_;
        }
        const __half* vb = kb + C_;
#pragma unroll
        for (int i = 0; i < 4; i++) {
            int idx = tid + i * 128;
            int r = idx >> 3;        // 0..63
            int c = idx & 7;
            uint32_t so = sw128((uint32_t)(r * 128 + c * 16));
            cpa16(st + so,        kb + (size_t)r * stride + c * 8);
            cpa16(st + 8192 + so, vb + (size_t)r * stride + c * 8);
        }
    };

    // Q tile: 128 rows x 128B (row stride 3C in gmem)
#pragma unroll
    for (int i = 0; i < 8; i++) {
        int idx = tid + i * 128;
        int r = idx >> 3;        // 0..127
        int c = idx & 7;
        cpa16(sQ + sw128((uint32_t)(r * 128 + c * 16)),
              qg + (size_t)r * 3 * C_ + c * 8);
    }
    prefetch(0, sStage);
    cpa_commit();
    prefetch(64, sStage + AT_STAGE);
    cpa_commit();

    const int lr = lane & 15;
    const int lc = (lane >> 4) << 4;
    const int w32 = wid * 32;
    const uint32_t xv = (uint32_t)((lr & 7) << 4);

    uint32_t rowo[4], colx[4];
#pragma unroll
    for (int ng = 0; ng < 4; ng++) rowo[ng] = (uint32_t)((ng * 16 + lr) * 128);
#pragma unroll
    for (int kk = 0; kk < 4; kk++) colx[kk] = ((uint32_t)(kk * 32 + lc)) ^ xv;

    uint32_t qf[2][4][4];
    float O[2][8][4];
#pragma unroll
    for (int mf = 0; mf < 2; mf++)
#pragma unroll
        for (int nt = 0; nt < 8; nt++)
#pragma unroll
            for (int t = 0; t < 4; t++) O[mf][nt][t] = 0.0f;
    float mrow[2][2], lrow[2][2];
#pragma unroll
    for (int mf = 0; mf < 2; mf++) {
        mrow[mf][0] = -1e30f; mrow[mf][1] = -1e30f;
        lrow[mf][0] = 0.0f;   lrow[mf][1] = 0.0f;
    }

    int stage = 0;
    for (int kt = 0; kt < KVT; kt++) {
        if (kt + 1 < KVT) cpa_wait<1>(); else cpa_wait<0>();
        __syncthreads();
        if (kt + 2 < KVT) {
            int ns = stage + 2; if (ns >= 3) ns -= 3;
            prefetch((kt + 2) * 64, sStage + ns * AT_STAGE);
            cpa_commit();
        }

        if (kt == 0) {
#pragma unroll
            for (int mf = 0; mf < 2; mf++) {
                const uint32_t qrow = sQ + (uint32_t)((w32 + mf * 16 + lr) * 128);
#pragma unroll
                for (int kk = 0; kk < 4; kk++)
                    ldsm_x4(qf[mf][kk], qrow + colx[kk]);
            }
        }

        const uint32_t tK = sStage + stage * AT_STAGE;
        const uint32_t tV = tK + 8192;

        // ---- S = Q . K^T (log2 domain) ----
        float S[2][8][4];
#pragma unroll
        for (int mf = 0; mf < 2; mf++)
#pragma unroll
            for (int nt = 0; nt < 8; nt++)
#pragma unroll
                for (int t = 0; t < 4; t++) S[mf][nt][t] = 0.0f;

#pragma unroll
        for (int kk = 0; kk < 4; kk++) {
            uint32_t bf[4][4];
#pragma unroll
            for (int ng = 0; ng < 4; ng++)
                ldsm_x4(bf[ng], tK + rowo[ng] + colx[kk]);
#pragma unroll
            for (int mf = 0; mf < 2; mf++)
#pragma unroll
                for (int ng = 0; ng < 4; ng++)
#pragma unroll
                    for (int s = 0; s < 2; s++)
                        mma_fp16(S[mf][ng * 2 + s], qf[mf][kk], bf[ng][s], bf[ng][2 + s]);
        }

        // ---- online softmax (base 2, fp32 ex2) — R10 structure ----
        uint32_t ph[2][4][4];
#pragma unroll
        for (int mf = 0; mf < 2; mf++) {
            float mt0 = -1e30f, mt1 = -1e30f;
#pragma unroll
            for (int nt = 0; nt < 8; nt++) {
                mt0 = fmaxf(mt0, fmaxf(S[mf][nt][0], S[mf][nt][1]));
                mt1 = fmaxf(mt1, fmaxf(S[mf][nt][2], S[mf][nt][3]));
            }
            mt0 = fmaxf(mt0, __shfl_xor_sync(0xffffffffu, mt0, 1));
            mt0 = fmaxf(mt0, __shfl_xor_sync(0xffffffffu, mt0, 2));
            mt1 = fmaxf(mt1, __shfl_xor_sync(0xffffffffu, mt1, 1));
            mt1 = fmaxf(mt1, __shfl_xor_sync(0xffffffffu, mt1, 2));

            float mn0 = fmaxf(mrow[mf][0], mt0), mn1 = fmaxf(mrow[mf][1], mt1);
            float a0 = fexp2(mrow[mf][0] - mn0), a1 = fexp2(mrow[mf][1] - mn1);
            mrow[mf][0] = mn0; mrow[mf][1] = mn1;

            float rs0 = 0.0f, rs1 = 0.0f;
#pragma unroll
            for (int nt = 0; nt < 8; nt++) {
                S[mf][nt][0] = fexp2(S[mf][nt][0] - mn0);
                S[mf][nt][1] = fexp2(S[mf][nt][1] - mn0);
                S[mf][nt][2] = fexp2(S[mf][nt][2] - mn1);
                S[mf][nt][3] = fexp2(S[mf][nt][3] - mn1);
                rs0 += S[mf][nt][0] + S[mf][nt][1];
                rs1 += S[mf][nt][2] + S[mf][nt][3];
            }
            rs0 += __shfl_xor_sync(0xffffffffu, rs0, 1);
            rs0 += __shfl_xor_sync(0xffffffffu, rs0, 2);
            rs1 += __shfl_xor_sync(0xffffffffu, rs1, 1);
            rs1 += __shfl_xor_sync(0xffffffffu, rs1, 2);
            lrow[mf][0] = lrow[mf][0] * a0 + rs0;
            lrow[mf][1] = lrow[mf][1] * a1 + rs1;

#pragma unroll
            for (int nt = 0; nt < 8; nt++) {
                O[mf][nt][0] *= a0; O[mf][nt][1] *= a0;
                O[mf][nt][2] *= a1; O[mf][nt][3] *= a1;
            }

#pragma unroll
            for (int j = 0; j < 4; j++) {
                ph[mf][j][0] = pack_h2(S[mf][2 * j][0],     S[mf][2 * j][1]);
                ph[mf][j][1] = pack_h2(S[mf][2 * j][2],     S[mf][2 * j][3]);
                ph[mf][j][2] = pack_h2(S[mf][2 * j + 1][0], S[mf][2 * j + 1][1]);
                ph[mf][j][3] = pack_h2(S[mf][2 * j + 1][2], S[mf][2 * j + 1][3]);
            }
        }

        // ---- O += P . V  (V [kv][d] via trans-ldsm; atom pairing (2s,2s+1)) ----
        // k-step j covers kv rows j*16..j*16+15 -> rowo[j]; n-group ng covers d ng*16..
#pragma unroll
        for (int j = 0; j < 4; j++) {
            uint32_t vf[4][4];
#pragma unroll
            for (int ng = 0; ng < 4; ng++)
                ldsm_x4_t(vf[ng], tV + rowo[j] + colx[ng]);
#pragma unroll
            for (int mf = 0; mf < 2; mf++)
#pragma unroll
                for (int ng = 0; ng < 4; ng++)
#pragma unroll
                    for (int s = 0; s < 2; s++)
                        mma_fp16(O[mf][ng * 2 + s], ph[mf][j], vf[ng][2 * s], vf[ng][2 * s + 1]);
        }
        if (++stage >= 3) stage = 0;
    }

    // ---- epilogue ----
    const int g  = lane >> 2;
    const int tg = lane & 3;
#pragma unroll
    for (int mf = 0; mf < 2; mf++) {
        const float inv0 = 1.0f / lrow[mf][0], inv1 = 1.0f / lrow[mf][1];
        const int n0 = qt * 128 + w32 + mf * 16 + g;
#pragma unroll
        for (int nt = 0; nt < 8; nt++) {
            const int col = h * D_ + nt * 8 + tg * 2;
            *(uint32_t*)(oh + (size_t)(b * N_ + n0) * C_ + col) =
                pack_h2(O[mf][nt][0] * inv0, O[mf][nt][1] * inv0);
            *(uint32_t*)(oh + (size_t)(b * N_ + n0 + 8) * C_ + col) =
                pack_h2(O[mf][nt][2] * inv1, O[mf][nt][3] * inv1);
        }
    }
}

// ---------------------------------------------------------------------------
extern "C" void kernel_launch(void* const* d_in, const int* in_sizes, int n_in,
                              void* d_out, int out_size) {
    const float* x      = (const float*)d_in[0];
    const float* ctx    = (const float*)d_in[1];
    const float* w_qkv  = (const float*)d_in[2];
    const float* w_proj = (const float*)d_in[3];
    const float* b_proj = (const float*)d_in[4];
    float* out = (float*)d_out;

    void *p;
    cudaGetSymbolAddress(&p, g_qkvh);  __half* qkvh = (__half*)p;
    cudaGetSymbolAddress(&p, g_ctxh);  __half* ctxh = (__half*)p;
    cudaGetSymbolAddress(&p, g_xh);    __half* xh   = (__half*)p;
    cudaGetSymbolAddress(&p, g_wqkv);  __half* wq   = (__half*)p;
    cudaGetSymbolAddress(&p, g_wproj); __half* wp   = (__half*)p;
    cudaGetSymbolAddress(&p, g_ah);    __half* ah   = (__half*)p;

    cudaFuncSetAttribute(gemm_mma<true>,  cudaFuncAttributeMaxDynamicSharedMemorySize, GEMM_SMEM);
    cudaFuncSetAttribute(gemm_mma<false>, cudaFuncAttributeMaxDynamicSharedMemorySize, GEMM_SMEM);
    cudaFuncSetAttribute(attn_mma,        cudaFuncAttributeMaxDynamicSharedMemorySize, AT_SMEM);

    // 0) convert ctx/x/weights to fp16 (Q-rows of w_qkv carry 0.125*log2e)
    decomp_all<<<(N4ALL + 255) / 256, 256>>>(ctx, x, w_qkv, w_proj,
                                             ctxh, xh, wq, wp);

    // 1) QKV projection -> fp16 qkv
    {
        dim3 grid(3 * C_ / 128, B_ * N_ / 128);
        gemm_mma<true><<<grid, 128, GEMM_SMEM>>>(xh, wq, nullptr, nullptr, qkvh,
                                                 B_ * N_, 3 * C_, C_);
    }

    // 2) Attention (reads K/V directly from ctxh/qkvh)
    {
        dim3 grid(N_ / 128, H_, B_);
        attn_mma<<<grid, 128, AT_SMEM>>>(qkvh, ctxh, ah);
    }

    // 3) Output projection with bias -> fp32 out
    {
        dim3 grid(C_ / 128, B_ * N_ / 128);
        gemm_mma<false><<<grid, 128, GEMM_SMEM>>>(ah, wp, b_proj, out, nullptr,
                                                  B_ * N_, C_, C_);
    }
}